// round 16
// baseline (speedup 1.0000x reference)
#include <cuda_runtime.h>
#include <math.h>

// YOLO loss — fused single launch. Warp-level TRIPLE-buffered cp.async
// pipeline (2 tiles in flight per warp) + register-prefetched mask/tbox.
// tcls streamed direct. Outputs 5 f32: total, reg, containing, noobj, cls.

#define S_GRID_INV (1.0f / 14.0f)
#define L_COORD 5.0f
#define L_NOOBJ 0.5f
#define TPB 128
#define NWARP (TPB / 32)
#define CPW 32                   // cells per warp-tile
#define TILE_FL (CPW * 30)       // 960 floats = 3840 B
#define TILE_CH (CPW * 120 / 16) // 240 x 16B chunks
#define NBUF 3

__device__ double g_acc[4];      // cls, noobj(raw), reg(raw), containing
__device__ unsigned g_counter;   // zero-init; reset by last block each run

__device__ __forceinline__ bool loadMask(const void* maskv, int mode,
                                         int c, int ncell) {
    if (c >= ncell) return false;
    if (mode == 0)  return ((const int*)maskv)[c] != 0;
    if (mode == 1)  return ((const unsigned char*)maskv)[c] != 0;
    return ((const float*)maskv)[c] != 0.0f;
}

__device__ __forceinline__ float4 loadTbox(const float* tbox, int c,
                                           int ncell, bool m) {
    if (m && c < ncell) return __ldcs(((const float4*)tbox) + c);
    return make_float4(0.f, 0.f, 0.f, 0.f);
}

// Stages tile (cellBase) if in range; ALWAYS commits a group so the
// outstanding-group count stays uniform for wait_group.
__device__ __forceinline__ void stageTile(const float* __restrict__ pred,
                                          int cellBase, int lane, int ncell,
                                          unsigned sbuf) {
    if (cellBase < ncell) {
        const char* gp = (const char*)(pred + (size_t)cellBase * 30);
        long long bytes = ((long long)ncell - cellBase) * 120;
#pragma unroll
        for (int k = 0; k < 8; k++) {
            int ch = lane + 32 * k;
            long long off = (long long)ch * 16;
            if (ch < TILE_CH && off < bytes)
                asm volatile("cp.async.cg.shared.global [%0], [%1], 16;\n"
                             :: "r"(sbuf + (unsigned)(ch * 16)), "l"(gp + off));
        }
    }
    asm volatile("cp.async.commit_group;\n");
}

__device__ __forceinline__ void computeTile(
    const float* buf, int cellBase, int lane, int ncell, bool m, float4 tb,
    const float* __restrict__ tcls,
    float& s_cls, float& s_noobj, float& s_reg, float& s_cont)
{
    const int c = cellBase + lane;
    if (c >= ncell) return;

    const float2* mp2 = (const float2*)(buf + lane * 30);   // 8B aligned

    if (!m) {
        float cf0 = mp2[2].x;    // pred float idx 4
        float cf1 = mp2[4].y;    // pred float idx 9
        s_noobj += cf0 * cf0 + cf1 * cf1;
        return;
    }

    float pv[10];
#pragma unroll
    for (int j = 0; j < 5; j++) {
        float2 v = mp2[j];
        pv[2 * j]     = v.x;
        pv[2 * j + 1] = v.y;
    }

    // ---- class loss: tcls streamed direct, pred classes from smem ----
    {
        const float4* tc4 = (const float4*)tcls + (size_t)c * 5;
        const float2* mc2 = (const float2*)(buf + lane * 30 + 10);
        float cls = 0.f;
#pragma unroll
        for (int j = 0; j < 5; j++) {
            float4 t = __ldcs(tc4 + j);
            float2 a = mc2[2 * j];
            float2 b = mc2[2 * j + 1];
            float d0 = t.x - a.x;
            float d1 = t.y - a.y;
            float d2 = t.z - b.x;
            float d3 = t.w - b.y;
            cls += d0 * d0 + d1 * d1 + d2 * d2 + d3 * d3;
        }
        s_cls += cls;
    }

    // ---- IoU of the two pred boxes vs target (tb prefetched in regs) ----
    float t_cx = tb.x * S_GRID_INV;
    float t_cy = tb.y * S_GRID_INV;
    float t_x1 = t_cx - 0.5f * tb.z;
    float t_y1 = t_cy - 0.5f * tb.w;
    float t_x2 = t_cx + 0.5f * tb.z;
    float t_y2 = t_cy + 0.5f * tb.w;
    float area_t = (t_x2 - t_x1) * (t_y2 - t_y1);

    float iou[2];
#pragma unroll
    for (int b = 0; b < 2; b++) {
        float px = pv[5 * b + 0] * S_GRID_INV;
        float py = pv[5 * b + 1] * S_GRID_INV;
        float pw = pv[5 * b + 2];
        float ph = pv[5 * b + 3];
        float p_x1 = px - 0.5f * pw;
        float p_y1 = py - 0.5f * ph;
        float p_x2 = px + 0.5f * pw;
        float p_y2 = py + 0.5f * ph;
        float lt_x = fmaxf(t_x1, p_x1);
        float lt_y = fmaxf(t_y1, p_y1);
        float rb_x = fminf(t_x2, p_x2);
        float rb_y = fminf(t_y2, p_y2);
        float w = fmaxf(rb_x - lt_x, 0.0f);
        float h = fmaxf(rb_y - lt_y, 0.0f);
        float inter = w * h;
        float area_p = (p_x2 - p_x1) * (p_y2 - p_y1);
        iou[b] = inter / (area_t + area_p - inter);
    }

    bool sel = iou[1] > iou[0];    // first max wins on tie
    float best_iou = sel ? iou[1] : iou[0];
    float bb_x = sel ? pv[5] : pv[0];
    float bb_y = sel ? pv[6] : pv[1];
    float bb_w = sel ? pv[7] : pv[2];
    float bb_h = sel ? pv[8] : pv[3];
    float bb_c = sel ? pv[9] : pv[4];

    float dx = bb_x - tb.x;
    float dy = bb_y - tb.y;
    float sw = sqrtf(bb_w) - sqrtf(tb.z);
    float sh = sqrtf(bb_h) - sqrtf(tb.w);
    s_reg += dx * dx + dy * dy + sw * sw + sh * sh;

    float dc = best_iou - bb_c;
    s_cont += dc * dc;
}

__global__ void __launch_bounds__(TPB, 4) yolo_fused_kernel(
    const float* __restrict__ pred,
    const float* __restrict__ tbox,
    const float* __restrict__ tcls,
    const void* __restrict__ maskv,
    int ncell, int n_batch, int ntiles, float* __restrict__ out)
{
    __shared__ float sp[NWARP][NBUF][TILE_FL];   // 46 KB
    __shared__ float sm[4][NWARP];
    __shared__ bool s_last;

    const int tid  = threadIdx.x;
    const int warp = tid >> 5;
    const int lane = tid & 31;
    const int gw = blockIdx.x * NWARP + warp;        // global warp id
    const int ws = gridDim.x * NWARP;

    unsigned sb[NBUF];
#pragma unroll
    for (int i = 0; i < NBUF; i++)
        sb[i] = (unsigned)__cvta_generic_to_shared(&sp[warp][i][0]);

    // ---- mask dtype detection: warp-local ballot over first 32 words ----
    int mode;
    {
        unsigned w0 = ((const unsigned*)maskv)[lane];
        bool gt1 = w0 > 1u;
        bool bad = ((w0 & 0xFFu) > 1u) | (((w0 >> 8) & 0xFFu) > 1u) |
                   (((w0 >> 16) & 0xFFu) > 1u) | ((w0 >> 24) > 1u);
        unsigned bg = __ballot_sync(0xFFFFFFFFu, gt1);
        unsigned bb = __ballot_sync(0xFFFFFFFFu, bad);
        mode = (bg == 0) ? 0 : (bb ? 2 : 1);
    }

    float s_cls = 0.f, s_noobj = 0.f, s_reg = 0.f, s_cont = 0.f;

    // ---- triple-buffered pipeline: 2 tiles in flight per warp ----
    int t = gw;
    if (t < ntiles) {
        // prologue: stage t -> b0, t+ws -> b1
        stageTile(pred, t * CPW, lane, ncell, sb[0]);
        bool mA = loadMask(maskv, mode, t * CPW + lane, ncell);
        float4 tbA = loadTbox(tbox, t * CPW + lane, ncell, mA);

        stageTile(pred, (t + ws) * CPW, lane, ncell, sb[1]);
        bool mB = loadMask(maskv, mode, (t + ws) * CPW + lane, ncell);
        float4 tbB = loadTbox(tbox, (t + ws) * CPW + lane, ncell, mB);

        int buf = 0;               // buffer holding tile t
        while (t < ntiles) {
            // stage t+2ws into buf (buf+2)%3 — always commits a group
            int t2 = t + 2 * ws;
            stageTile(pred, t2 * CPW, lane, ncell, sb[(buf + 2) % NBUF]);

            // wait: 3 groups outstanding -> oldest (tile t) complete
            asm volatile("cp.async.wait_group 2;\n" ::: "memory");
            __syncwarp();

            computeTile(&sp[warp][buf][0], t * CPW, lane, ncell, mA, tbA,
                        tcls, s_cls, s_noobj, s_reg, s_cont);

            // rotate state; prefetch mask/tbox for t+2ws
            mA = mB; tbA = tbB;
            mB = loadMask(maskv, mode, t2 * CPW + lane, ncell);
            tbB = loadTbox(tbox, t2 * CPW + lane, ncell, mB);

            t += ws;
            buf = (buf + 1) % NBUF;
            __syncwarp();          // lanes done with old buffer before restage
        }
        asm volatile("cp.async.wait_group 0;\n" ::: "memory");
    }

    // ---- warp reduction, then block reduction ----
#pragma unroll
    for (int off = 16; off; off >>= 1) {
        s_cls   += __shfl_down_sync(0xFFFFFFFFu, s_cls,   off);
        s_noobj += __shfl_down_sync(0xFFFFFFFFu, s_noobj, off);
        s_reg   += __shfl_down_sync(0xFFFFFFFFu, s_reg,   off);
        s_cont  += __shfl_down_sync(0xFFFFFFFFu, s_cont,  off);
    }
    if (lane == 0) {
        sm[0][warp] = s_cls;
        sm[1][warp] = s_noobj;
        sm[2][warp] = s_reg;
        sm[3][warp] = s_cont;
    }
    __syncthreads();

    if (tid == 0) {
        float a0 = 0.f, a1 = 0.f, a2 = 0.f, a3 = 0.f;
#pragma unroll
        for (int w = 0; w < NWARP; w++) {
            a0 += sm[0][w];
            a1 += sm[1][w];
            a2 += sm[2][w];
            a3 += sm[3][w];
        }
        atomicAdd(&g_acc[0], (double)a0);
        atomicAdd(&g_acc[1], (double)a1);
        atomicAdd(&g_acc[2], (double)a2);
        atomicAdd(&g_acc[3], (double)a3);

        __threadfence();
        unsigned old = atomicAdd(&g_counter, 1u);
        s_last = (old == gridDim.x - 1);
    }
    __syncthreads();

    // ---- last block: finalize + reset persistent state ----
    if (s_last && tid == 0) {
        double cls   = atomicAdd(&g_acc[0], 0.0);
        double noobj = (double)L_NOOBJ * atomicAdd(&g_acc[1], 0.0);
        double reg   = (double)L_COORD * atomicAdd(&g_acc[2], 0.0);
        double cont  = atomicAdd(&g_acc[3], 0.0);
        double total = (cls + noobj + reg + cont) / (double)n_batch;
        out[0] = (float)total;
        out[1] = (float)reg;
        out[2] = (float)cont;
        out[3] = (float)noobj;
        out[4] = (float)cls;
        g_acc[0] = 0.0; g_acc[1] = 0.0; g_acc[2] = 0.0; g_acc[3] = 0.0;
        __threadfence();
        g_counter = 0u;
    }
}

extern "C" void kernel_launch(void* const* d_in, const int* in_sizes, int n_in,
                              void* d_out, int out_size) {
    // Identify inputs by element count: pred = 30n, tcls = 20n, tbox = 4n, mask = n
    const void* ptrs[4] = {d_in[0], d_in[1], d_in[2], d_in[3]};
    long long sz[4] = {in_sizes[0], in_sizes[1], in_sizes[2], in_sizes[3]};

    int im = 0;
    for (int i = 1; i < 4; i++) if (sz[i] < sz[im]) im = i;
    long long n = sz[im];

    const float* pred = nullptr;
    const float* tbox = nullptr;
    const float* tcls = nullptr;
    const void*  hmask = ptrs[im];
    for (int i = 0; i < 4; i++) {
        if (i == im) continue;
        if (sz[i] == 30 * n) pred = (const float*)ptrs[i];
        else if (sz[i] == 20 * n) tcls = (const float*)ptrs[i];
        else if (sz[i] == 4 * n) tbox = (const float*)ptrs[i];
    }

    int ncell = (int)n;                   // 802816
    int n_batch = ncell / (14 * 14);      // 4096
    int ntiles = (ncell + CPW - 1) / CPW; // 25088

    int dev = 0, nsm = 148;
    cudaGetDevice(&dev);
    cudaDeviceGetAttribute(&nsm, cudaDevAttrMultiProcessorCount, dev);

    int blocks = nsm * 4;                 // 4 blocks/SM (46KB smem each)
    int maxBlocks = (ntiles + NWARP - 1) / NWARP;
    if (blocks > maxBlocks) blocks = maxBlocks;

    yolo_fused_kernel<<<blocks, TPB>>>(pred, tbox, tcls, hmask,
                                       ncell, n_batch, ntiles, (float*)d_out);
}